// round 7
// baseline (speedup 1.0000x reference)
#include <cuda_runtime.h>

typedef unsigned long long u64;

// ---------- packed f32x2 helpers ----------
__device__ __forceinline__ u64 fma2(u64 a, u64 b, u64 c){
    u64 d; asm("fma.rn.f32x2 %0, %1, %2, %3;" : "=l"(d) : "l"(a), "l"(b), "l"(c)); return d;
}
__device__ __forceinline__ u64 mul2(u64 a, u64 b){
    u64 d; asm("mul.rn.f32x2 %0, %1, %2;" : "=l"(d) : "l"(a), "l"(b)); return d;
}
__device__ __forceinline__ u64 pk2(float lo, float hi){
    u64 d; asm("mov.b64 %0, {%1, %2};" : "=l"(d) : "f"(lo), "f"(hi)); return d;
}
__device__ __forceinline__ void upk2(u64 v, float& lo, float& hi){
    asm("mov.b64 {%0, %1}, %2;" : "=f"(lo), "=f"(hi) : "l"(v));
}

// leaky_relu(x) = 0.505*x + 0.495*|x| (slope 0.01), fully packed
__device__ __forceinline__ u64 act_lrelu(u64 v){
    u64 av = v & 0x7FFFFFFF7FFFFFFFULL;
    return fma2(av, 0x3EFD70A43EFD70A4ULL /*0.495*/, mul2(v, 0x3F0147AE3F0147AEULL /*0.505*/));
}
__device__ __forceinline__ float tanh_ap(float x){
    float r; asm("tanh.approx.f32 %0, %1;" : "=f"(r) : "f"(x)); return r;
}
// hidden-layer sigmoid: 0.5*tanh(x/2)+0.5  (tanh.approx, err attenuated downstream)
__device__ __forceinline__ u64 act_sigt(u64 v){
    const u64 half2 = 0x3F0000003F000000ULL;
    u64 v2 = mul2(v, half2);
    float lo, hi; upk2(v2, lo, hi);
    return fma2(pk2(tanh_ap(lo), tanh_ap(hi)), half2, half2);
}
// final-layer sigmoid: near-exact ex2+rcp
__device__ __forceinline__ float fast_sigmoid(float x){
    float e; asm("ex2.approx.f32 %0, %1;" : "=f"(e) : "f"(-1.44269504088896341f * x));
    float r; asm("rcp.approx.f32 %0, %1;" : "=f"(r) : "f"(1.0f + e));
    return r;
}
__device__ __forceinline__ u64 act_sige(u64 v){
    float lo, hi; upk2(v, lo, hi);
    return pk2(fast_sigmoid(lo), fast_sigmoid(hi));
}
template<int ACT> __device__ __forceinline__ u64 act(u64 v){
    if (ACT == 0) return act_lrelu(v);
    else if (ACT == 1) return act_sigt(v);
    else return act_sige(v);
}

// ---------- X-macro lists ----------
#define QLIST(F) F(0,0,1) F(1,2,3) F(2,4,5) F(3,6,7) F(4,8,9) \
                 F(5,10,11) F(6,12,13) F(7,14,15) F(8,16,17) F(9,18,19)
#define ACC20(F) F(0) F(1) F(2) F(3) F(4) F(5) F(6) F(7) F(8) F(9) \
                 F(10) F(11) F(12) F(13) F(14) F(15) F(16) F(17) F(18) F(19)

// scatter one L2 input (packed per-item pairs tt_ab, tt_cd) across all 20 outputs
#define SCATQ(q,a,b1) { ulonglong2 w = rr[q]; \
    Aab##a  = fma2(tt_ab, w.x, Aab##a );  Acd##a  = fma2(tt_cd, w.x, Acd##a ); \
    Aab##b1 = fma2(tt_ab, w.y, Aab##b1);  Acd##b1 = fma2(tt_cd, w.y, Acd##b1); }

// ---------- one full 3-layer path, FOUR batch items (pairs AB, CD) ----------
// shared block (ulonglong2 units), all weights duplicated (w,w) per lane-pair:
//   L1 @0 (75): p-th triple {B,W0,W1}, each = ((v_{2p},v_{2p}),(v_{2p+1},v_{2p+1}))
//   L2 bias @75 (10), L2 weights @85 (500): row i at 85+10i
//   L3 @585 (21): [0]=((b0,b0),(b1,b1)), [1+i]=((W[i][0]dup),(W[i][1]dup))
template<int ACT, int ACTF>
__device__ __forceinline__ void path4(const ulonglong2* __restrict__ sb,
                                      u64& H0ab, u64& H1ab, u64& H0cd, u64& H1cd)
{
    const ulonglong2* l1p = sb;
    const ulonglong2* b2p = sb + 75;
    const ulonglong2* w2p = sb + 85;
    const ulonglong2* l3p = sb + 585;

    #define DECLA(q,a,b1) u64 Aab##a, Acd##a, Aab##b1, Acd##b1;
    QLIST(DECLA)
    #undef DECLA
    #define INITA(q,a,b1) { ulonglong2 t = b2p[q]; \
        Aab##a = t.x; Acd##a = t.x; Aab##b1 = t.y; Acd##b1 = t.y; }
    QLIST(INITA)
    #undef INITA

    #pragma unroll 1
    for (int p = 0; p < 25; p++){
        const ulonglong2* t1 = l1p + 3*p;
        ulonglong2 Bq = t1[0], W0 = t1[1], W1 = t1[2];
        u64 tab0 = act<ACT>(fma2(H1ab, W1.x, fma2(H0ab, W0.x, Bq.x)));
        u64 tcd0 = act<ACT>(fma2(H1cd, W1.x, fma2(H0cd, W0.x, Bq.x)));
        u64 tab1 = act<ACT>(fma2(H1ab, W1.y, fma2(H0ab, W0.y, Bq.y)));
        u64 tcd1 = act<ACT>(fma2(H1cd, W1.y, fma2(H0cd, W0.y, Bq.y)));
        {
            u64 tt_ab = tab0, tt_cd = tcd0;
            const ulonglong2* rr = w2p + 20*p;
            QLIST(SCATQ)
        }
        {
            u64 tt_ab = tab1, tt_cd = tcd1;
            const ulonglong2* rr = w2p + 20*p + 10;
            QLIST(SCATQ)
        }
    }

    #define ACTA(q,a,b1) Aab##a = act<ACT>(Aab##a); Acd##a = act<ACT>(Acd##a); \
                         Aab##b1 = act<ACT>(Aab##b1); Acd##b1 = act<ACT>(Acd##b1);
    QLIST(ACTA)
    #undef ACTA

    u64 r0ab, r1ab, r0cd, r1cd;
    { ulonglong2 b = l3p[0]; r0ab = b.x; r1ab = b.y; r0cd = b.x; r1cd = b.y; }
    #define L3Q(i) { ulonglong2 w = l3p[1+(i)]; \
        r0ab = fma2(Aab##i, w.x, r0ab);  r1ab = fma2(Aab##i, w.y, r1ab); \
        r0cd = fma2(Acd##i, w.x, r0cd);  r1cd = fma2(Acd##i, w.y, r1cd); }
    ACC20(L3Q)
    #undef L3Q

    H0ab = act<ACTF>(r0ab);
    H1ab = act<ACTF>(r1ab);
    H0cd = act<ACTF>(r0cd);
    H1cd = act<ACTF>(r1cd);
}

// ---------- shared fill: 2424 floats per path block ----------
__device__ void fill_path(float* d,
                          const float* __restrict__ W1, const float* __restrict__ b1,
                          const float* __restrict__ W2, const float* __restrict__ b2,
                          const float* __restrict__ W3, const float* __restrict__ b3)
{
    for (int e = threadIdx.x; e < 2424; e += blockDim.x){
        float v;
        if (e < 300){                       // L1 triples
            int p = e / 12, k = e % 12;
            int j = 2*p + ((k >> 1) & 1);
            v = (k < 4) ? b1[j] : (k < 8) ? W1[j] : W1[50 + j];
        } else if (e < 340){                // L2 bias
            int r = e - 300;
            int j = 2*(r/4) + ((r >> 1) & 1);
            v = b2[j];
        } else if (e < 2340){               // L2 weights
            int r = e - 340;
            int i = r / 40, s = r % 40;
            int j = 2*(s/4) + ((s >> 1) & 1);
            v = W2[i*20 + j];
        } else {                            // L3
            int r = e - 2340;
            int idx = r / 4, j = (r >> 1) & 1;
            v = (idx == 0) ? b3[j] : W3[(idx-1)*2 + j];
        }
        d[e] = v;
    }
}

__global__ void __launch_bounds__(128, 3)
recurrent_kernel(const float2* __restrict__ win,
                 const float* __restrict__ Wh1, const float* __restrict__ bh1,
                 const float* __restrict__ Wh2, const float* __restrict__ bh2,
                 const float* __restrict__ Wh3, const float* __restrict__ bh3,
                 const float* __restrict__ Wz1, const float* __restrict__ bz1,
                 const float* __restrict__ Wz2, const float* __restrict__ bz2,
                 const float* __restrict__ Wz3, const float* __restrict__ bz3,
                 float2* __restrict__ out, int Q)
{
    __shared__ ulonglong2 sH[606];
    __shared__ ulonglong2 sZ[606];
    fill_path((float*)sH, Wh1, bh1, Wh2, bh2, Wh3, bh3);
    fill_path((float*)sZ, Wz1, bz1, Wz2, bz2, Wz3, bz3);
    __syncthreads();

    int tid = blockIdx.x * blockDim.x + threadIdx.x;
    if (tid >= Q) return;

    float2 hA = win[tid];
    float2 hB = win[tid + Q];
    float2 hC = win[tid + 2*Q];
    float2 hD = win[tid + 3*Q];
    u64 H0ab = pk2(hA.x, hB.x), H1ab = pk2(hA.y, hB.y);
    u64 H0cd = pk2(hC.x, hD.x), H1cd = pk2(hC.y, hD.y);

    float2* opA = out + (size_t)tid * 19;
    float2* opB = out + ((size_t)tid +     Q) * 19;
    float2* opC = out + ((size_t)tid + 2*(size_t)Q) * 19;
    float2* opD = out + ((size_t)tid + 3*(size_t)Q) * 19;

    #pragma unroll 1
    for (int t = 0; t < 19; t++){
        // h path: leaky relu (hidden + final)
        path4<0, 0>(sH, H0ab, H1ab, H0cd, H1cd);
        // z path: tanh-sigmoid hidden, exact sigmoid final
        u64 Z0ab = H0ab, Z1ab = H1ab, Z0cd = H0cd, Z1cd = H1cd;
        path4<1, 2>(sZ, Z0ab, Z1ab, Z0cd, Z1cd);

        float zA0, zB0, zA1, zB1, zC0, zD0, zC1, zD1;
        upk2(Z0ab, zA0, zB0); upk2(Z1ab, zA1, zB1);
        upk2(Z0cd, zC0, zD0); upk2(Z1cd, zC1, zD1);
        opA[t] = make_float2(zA0, zA1);
        opB[t] = make_float2(zB0, zB1);
        opC[t] = make_float2(zC0, zC1);
        opD[t] = make_float2(zD0, zD1);
    }
}

extern "C" void kernel_launch(void* const* d_in, const int* in_sizes, int n_in,
                              void* d_out, int out_size)
{
    const float* w   = (const float*)d_in[0];
    const float* Wh1 = (const float*)d_in[1];
    const float* bh1 = (const float*)d_in[2];
    const float* Wh2 = (const float*)d_in[3];
    const float* bh2 = (const float*)d_in[4];
    const float* Wh3 = (const float*)d_in[5];
    const float* bh3 = (const float*)d_in[6];
    const float* Wz1 = (const float*)d_in[7];
    const float* bz1 = (const float*)d_in[8];
    const float* Wz2 = (const float*)d_in[9];
    const float* bz2 = (const float*)d_in[10];
    const float* Wz3 = (const float*)d_in[11];
    const float* bz3 = (const float*)d_in[12];

    int B = in_sizes[0] / 2;
    int Q = B / 4;                       // B = 1048576
    int threads = 128;
    int blocks = (Q + threads - 1) / threads;
    recurrent_kernel<<<blocks, threads>>>((const float2*)w,
                                          Wh1, bh1, Wh2, bh2, Wh3, bh3,
                                          Wz1, bz1, Wz2, bz2, Wz3, bz3,
                                          (float2*)d_out, Q);
}

// round 8
// speedup vs baseline: 1.0088x; 1.0088x over previous
#include <cuda_runtime.h>

typedef unsigned long long u64;

// ---------- packed f32x2 helpers ----------
__device__ __forceinline__ u64 fma2(u64 a, u64 b, u64 c){
    u64 d; asm("fma.rn.f32x2 %0, %1, %2, %3;" : "=l"(d) : "l"(a), "l"(b), "l"(c)); return d;
}
__device__ __forceinline__ u64 mul2(u64 a, u64 b){
    u64 d; asm("mul.rn.f32x2 %0, %1, %2;" : "=l"(d) : "l"(a), "l"(b)); return d;
}
__device__ __forceinline__ u64 pk2(float lo, float hi){
    u64 d; asm("mov.b64 %0, {%1, %2};" : "=l"(d) : "f"(lo), "f"(hi)); return d;
}
__device__ __forceinline__ void upk2(u64 v, float& lo, float& hi){
    asm("mov.b64 {%0, %1}, %2;" : "=f"(lo), "=f"(hi) : "l"(v));
}
__device__ __forceinline__ u64 dup2(float f){ return pk2(f, f); }

// leaky_relu(x) = 0.505*x + 0.495*|x| (slope 0.01), fully packed
__device__ __forceinline__ u64 act_lrelu(u64 v){
    u64 av = v & 0x7FFFFFFF7FFFFFFFULL;
    return fma2(av, 0x3EFD70A43EFD70A4ULL /*0.495*/, mul2(v, 0x3F0147AE3F0147AEULL /*0.505*/));
}
__device__ __forceinline__ float tanh_ap(float x){
    float r; asm("tanh.approx.f32 %0, %1;" : "=f"(r) : "f"(x)); return r;
}
// hidden-layer sigmoid: 0.5*tanh(x/2)+0.5  (2 MUFU instead of 4)
__device__ __forceinline__ u64 act_sigt(u64 v){
    const u64 half2 = 0x3F0000003F000000ULL;
    u64 v2 = mul2(v, half2);
    float lo, hi; upk2(v2, lo, hi);
    return fma2(pk2(tanh_ap(lo), tanh_ap(hi)), half2, half2);
}
// final-layer sigmoid: near-exact ex2+rcp
__device__ __forceinline__ float fast_sigmoid(float x){
    float e; asm("ex2.approx.f32 %0, %1;" : "=f"(e) : "f"(-1.44269504088896341f * x));
    float r; asm("rcp.approx.f32 %0, %1;" : "=f"(r) : "f"(1.0f + e));
    return r;
}
__device__ __forceinline__ u64 act_sige(u64 v){
    float lo, hi; upk2(v, lo, hi);
    return pk2(fast_sigmoid(lo), fast_sigmoid(hi));
}
// ACT codes: 0 = lrelu, 1 = tanh-sigmoid (hidden), 2 = exact sigmoid (final)
template<int ACT> __device__ __forceinline__ u64 act(u64 v){
    if (ACT == 0) return act_lrelu(v);
    else if (ACT == 1) return act_sigt(v);
    else return act_sige(v);
}

// scatter one loaded quad into both items' accumulator pairs
#define SCAT(qv, a0, a1) \
    CA##a0 = fma2(ddA, (qv).x, CA##a0);  CB##a0 = fma2(ddB, (qv).x, CB##a0); \
    CA##a1 = fma2(ddA, (qv).y, CA##a1);  CB##a1 = fma2(ddB, (qv).y, CB##a1);

// layer-3 step for one accumulator pair (rows 2i, 2i+1), both items
#define L3STEP(Ci, wlo_idx) { \
    float loA, hiA, loB, hiB; \
    upk2(CA##Ci, loA, hiA); upk2(CB##Ci, loB, hiB); \
    u64 wl = W3B[wlo_idx], wh = W3B[(wlo_idx)+1]; \
    resA = fma2(dup2(loA), wl, resA);  resB = fma2(dup2(loB), wl, resB); \
    resA = fma2(dup2(hiA), wh, resA);  resB = fma2(dup2(hiB), wh, resB); }

// ---------- one full 3-layer path, two batch items at once ----------
// W1B: 25 pairs x 2 ulonglong2: [ (bias_pair | w_row0_pair), (w_row1_pair | pad) ]
// W2B: [bias: 5 quads][row r: 5 quads each], r = 0..49
// W3B: [bias pair][row r pair], r = 0..19   (u64 units)
template<int ACT, int ACTF>
__device__ __forceinline__ void path2(const ulonglong2* __restrict__ W1B,
                                      const ulonglong2* __restrict__ W2B,
                                      const u64* __restrict__ W3B,
                                      u64& hA, u64& hB)
{
    float xa0, xa1, xb0, xb1;
    upk2(hA, xa0, xa1); upk2(hB, xb0, xb1);
    u64 D0A = dup2(xa0), D1A = dup2(xa1);
    u64 D0B = dup2(xb0), D1B = dup2(xb1);

    u64 CA0, CA1, CA2, CA3, CA4, CA5, CA6, CA7, CA8, CA9;
    u64 CB0, CB1, CB2, CB3, CB4, CB5, CB6, CB7, CB8, CB9;
    { ulonglong2 b = W2B[0]; CA0 = b.x; CA1 = b.y; CB0 = b.x; CB1 = b.y; }
    { ulonglong2 b = W2B[1]; CA2 = b.x; CA3 = b.y; CB2 = b.x; CB3 = b.y; }
    { ulonglong2 b = W2B[2]; CA4 = b.x; CA5 = b.y; CB4 = b.x; CB5 = b.y; }
    { ulonglong2 b = W2B[3]; CA6 = b.x; CA7 = b.y; CB6 = b.x; CB7 = b.y; }
    { ulonglong2 b = W2B[4]; CA8 = b.x; CA9 = b.y; CB8 = b.x; CB9 = b.y; }

    const ulonglong2* p1 = W1B;
    const ulonglong2* p2 = W2B + 5;

    #pragma unroll 1
    for (int p = 0; p < 25; p++){
        // layer-1 output pair (outputs 2p, 2p+1) for both items
        ulonglong2 bw = p1[0];
        u64 w1 = ((const u64*)p1)[2];
        p1 += 2;
        u64 axA = fma2(D0A, bw.y, bw.x); axA = fma2(D1A, w1, axA); axA = act<ACT>(axA);
        u64 axB = fma2(D0B, bw.y, bw.x); axB = fma2(D1B, w1, axB); axB = act<ACT>(axB);
        float f0A, f1A, f0B, f1B;
        upk2(axA, f0A, f1A); upk2(axB, f0B, f1B);

        // scatter row 2p
        {
            u64 ddA = dup2(f0A), ddB = dup2(f0B);
            ulonglong2 q;
            q = p2[0]; SCAT(q, 0, 1)
            q = p2[1]; SCAT(q, 2, 3)
            q = p2[2]; SCAT(q, 4, 5)
            q = p2[3]; SCAT(q, 6, 7)
            q = p2[4]; SCAT(q, 8, 9)
        }
        // scatter row 2p+1
        {
            u64 ddA = dup2(f1A), ddB = dup2(f1B);
            ulonglong2 q;
            q = p2[5]; SCAT(q, 0, 1)
            q = p2[6]; SCAT(q, 2, 3)
            q = p2[7]; SCAT(q, 4, 5)
            q = p2[8]; SCAT(q, 6, 7)
            q = p2[9]; SCAT(q, 8, 9)
        }
        p2 += 10;
    }

    CA0 = act<ACT>(CA0); CA1 = act<ACT>(CA1); CA2 = act<ACT>(CA2); CA3 = act<ACT>(CA3);
    CA4 = act<ACT>(CA4); CA5 = act<ACT>(CA5); CA6 = act<ACT>(CA6); CA7 = act<ACT>(CA7);
    CA8 = act<ACT>(CA8); CA9 = act<ACT>(CA9);
    CB0 = act<ACT>(CB0); CB1 = act<ACT>(CB1); CB2 = act<ACT>(CB2); CB3 = act<ACT>(CB3);
    CB4 = act<ACT>(CB4); CB5 = act<ACT>(CB5); CB6 = act<ACT>(CB6); CB7 = act<ACT>(CB7);
    CB8 = act<ACT>(CB8); CB9 = act<ACT>(CB9);

    // layer 3: 20 inputs -> 1 packed output pair, both items
    u64 resA = W3B[0];
    u64 resB = resA;
    L3STEP(0,  1)
    L3STEP(1,  3)
    L3STEP(2,  5)
    L3STEP(3,  7)
    L3STEP(4,  9)
    L3STEP(5, 11)
    L3STEP(6, 13)
    L3STEP(7, 15)
    L3STEP(8, 17)
    L3STEP(9, 19)

    hA = act<ACTF>(resA);
    hB = act<ACTF>(resB);
}

// ---------- shared fills (element-wise scalar, no per-thread arrays) ----------
// L1 block: 25 pairs x 8 floats: {b[2p],b[2p+1], W[0][2p],W[0][2p+1], W[1][2p],W[1][2p+1], 0,0}
__device__ void fill_L1(float* dstf, const float* __restrict__ W,
                        const float* __restrict__ Bv)
{
    for (int e = threadIdx.x; e < 200; e += blockDim.x){
        int p = e >> 3, k = e & 7;
        float v = 0.0f;
        if      (k < 2) v = Bv[2*p + k];
        else if (k < 4) v = W[      2*p + (k-2)];   // row 0 of W[2][50]
        else if (k < 6) v = W[50 +  2*p + (k-4)];   // row 1
        dstf[e] = v;
    }
}
// L2 block (float view): [bias: 20][row r: 20 floats], r=0..49
__device__ void fill_L2(float* dstf, const float* __restrict__ W,
                        const float* __restrict__ Bv)
{
    for (int e = threadIdx.x; e < 1020; e += blockDim.x){
        int blk = e / 20, j = e % 20;
        dstf[e] = (blk == 0) ? Bv[j] : W[(blk - 1) * 20 + j];
    }
}
// L3 block (float view): [b0,b1][row r: W[2r], W[2r+1]], r=0..19
__device__ void fill_L3(float* dstf, const float* __restrict__ W,
                        const float* __restrict__ Bv)
{
    for (int e = threadIdx.x; e < 42; e += blockDim.x){
        int blk = e >> 1, j = e & 1;
        dstf[e] = (blk == 0) ? Bv[j] : W[(blk - 1) * 2 + j];
    }
}

// shared layout (ulonglong2 units): H1@0(50)  H2@50(255)  Z1@305(50)  Z2@355(255)
__global__ void __launch_bounds__(128, 3)
recurrent_kernel(const float2* __restrict__ win,
                 const float* __restrict__ Wh1, const float* __restrict__ bh1,
                 const float* __restrict__ Wh2, const float* __restrict__ bh2,
                 const float* __restrict__ Wh3, const float* __restrict__ bh3,
                 const float* __restrict__ Wz1, const float* __restrict__ bz1,
                 const float* __restrict__ Wz2, const float* __restrict__ bz2,
                 const float* __restrict__ Wz3, const float* __restrict__ bz3,
                 float2* __restrict__ out, int half)
{
    __shared__ ulonglong2 sQ[610];
    __shared__ u64 sP[44];     // H3 @0 (21), Z3 @22 (21)

    fill_L1((float*)(sQ +   0), Wh1, bh1);
    fill_L2((float*)(sQ +  50), Wh2, bh2);
    fill_L1((float*)(sQ + 305), Wz1, bz1);
    fill_L2((float*)(sQ + 355), Wz2, bz2);
    fill_L3((float*)(sP +   0), Wh3, bh3);
    fill_L3((float*)(sP +  22), Wz3, bz3);
    __syncthreads();

    int tid = blockIdx.x * blockDim.x + threadIdx.x;
    if (tid >= half) return;

    float2 hinA = win[tid];
    float2 hinB = win[tid + half];
    u64 hA = pk2(hinA.x, hinA.y);
    u64 hB = pk2(hinB.x, hinB.y);

    float2* opA = out + (size_t)tid * 19;
    float2* opB = out + ((size_t)tid + half) * 19;

    #pragma unroll 1
    for (int t = 0; t < 19; t++){
        path2<0, 0>(sQ +   0, sQ +  50, sP +  0, hA, hB);   // h path: leaky relu
        u64 zA = hA, zB = hB;
        path2<1, 2>(sQ + 305, sQ + 355, sP + 22, zA, zB);   // z: tanh hidden, exact final
        float lo, hi;
        upk2(zA, lo, hi); opA[t] = make_float2(lo, hi);
        upk2(zB, lo, hi); opB[t] = make_float2(lo, hi);
    }
}

extern "C" void kernel_launch(void* const* d_in, const int* in_sizes, int n_in,
                              void* d_out, int out_size)
{
    const float* w   = (const float*)d_in[0];
    const float* Wh1 = (const float*)d_in[1];
    const float* bh1 = (const float*)d_in[2];
    const float* Wh2 = (const float*)d_in[3];
    const float* bh2 = (const float*)d_in[4];
    const float* Wh3 = (const float*)d_in[5];
    const float* bh3 = (const float*)d_in[6];
    const float* Wz1 = (const float*)d_in[7];
    const float* bz1 = (const float*)d_in[8];
    const float* Wz2 = (const float*)d_in[9];
    const float* bz2 = (const float*)d_in[10];
    const float* Wz3 = (const float*)d_in[11];
    const float* bz3 = (const float*)d_in[12];

    int B = in_sizes[0] / 2;
    int half = B / 2;                 // B = 1048576, even
    int threads = 128;
    int blocks = (half + threads - 1) / threads;
    recurrent_kernel<<<blocks, threads>>>((const float2*)w,
                                          Wh1, bh1, Wh2, bh2, Wh3, bh3,
                                          Wz1, bz1, Wz2, bz2, Wz3, bz3,
                                          (float2*)d_out, half);
}

// round 9
// speedup vs baseline: 1.1697x; 1.1594x over previous
#include <cuda_runtime.h>

typedef unsigned long long u64;

// ---------- packed f32x2 helpers ----------
__device__ __forceinline__ u64 fma2(u64 a, u64 b, u64 c){
    u64 d; asm("fma.rn.f32x2 %0, %1, %2, %3;" : "=l"(d) : "l"(a), "l"(b), "l"(c)); return d;
}
__device__ __forceinline__ u64 mul2(u64 a, u64 b){
    u64 d; asm("mul.rn.f32x2 %0, %1, %2;" : "=l"(d) : "l"(a), "l"(b)); return d;
}
__device__ __forceinline__ u64 pk2(float lo, float hi){
    u64 d; asm("mov.b64 %0, {%1, %2};" : "=l"(d) : "f"(lo), "f"(hi)); return d;
}
__device__ __forceinline__ void upk2(u64 v, float& lo, float& hi){
    asm("mov.b64 {%0, %1}, %2;" : "=f"(lo), "=f"(hi) : "l"(v));
}
__device__ __forceinline__ u64 dup2(float f){ return pk2(f, f); }

// leaky_relu(x) = 0.505*x + 0.495*|x| (slope 0.01), fully packed
__device__ __forceinline__ u64 act_lrelu(u64 v){
    u64 av = v & 0x7FFFFFFF7FFFFFFFULL;
    return fma2(av, 0x3EFD70A43EFD70A4ULL /*0.495*/, mul2(v, 0x3F0147AE3F0147AEULL /*0.505*/));
}
__device__ __forceinline__ float tanh_ap(float x){
    float r; asm("tanh.approx.f32 %0, %1;" : "=f"(r) : "f"(x)); return r;
}
// hidden-layer sigmoid: 0.5*tanh(x/2)+0.5  (2 MUFU per pair instead of 4)
__device__ __forceinline__ u64 act_sigt(u64 v){
    const u64 half2 = 0x3F0000003F000000ULL;
    u64 v2 = mul2(v, half2);
    float lo, hi; upk2(v2, lo, hi);
    return fma2(pk2(tanh_ap(lo), tanh_ap(hi)), half2, half2);
}
// final-layer sigmoid: near-exact ex2+rcp
__device__ __forceinline__ float fast_sigmoid(float x){
    float e; asm("ex2.approx.f32 %0, %1;" : "=f"(e) : "f"(-1.44269504088896341f * x));
    float r; asm("rcp.approx.f32 %0, %1;" : "=f"(r) : "f"(1.0f + e));
    return r;
}
__device__ __forceinline__ u64 act_sige(u64 v){
    float lo, hi; upk2(v, lo, hi);
    return pk2(fast_sigmoid(lo), fast_sigmoid(hi));
}
// ACT codes: 0 = lrelu, 1 = tanh-sigmoid (hidden), 2 = exact sigmoid (final)
template<int ACT> __device__ __forceinline__ u64 act(u64 v){
    if (ACT == 0) return act_lrelu(v);
    else if (ACT == 1) return act_sigt(v);
    else return act_sige(v);
}

// scatter one loaded quad into both items' accumulator pairs
#define SCAT(qv, a0, a1) \
    CA##a0 = fma2(ddA, (qv).x, CA##a0);  CB##a0 = fma2(ddB, (qv).x, CB##a0); \
    CA##a1 = fma2(ddA, (qv).y, CA##a1);  CB##a1 = fma2(ddB, (qv).y, CB##a1);

// layer-3 step for one accumulator pair (rows 2i, 2i+1), both items
#define L3STEP(Ci, wlo_idx) { \
    float loA, hiA, loB, hiB; \
    upk2(CA##Ci, loA, hiA); upk2(CB##Ci, loB, hiB); \
    u64 wl = W3B[wlo_idx], wh = W3B[(wlo_idx)+1]; \
    resA = fma2(dup2(loA), wl, resA);  resB = fma2(dup2(loB), wl, resB); \
    resA = fma2(dup2(hiA), wh, resA);  resB = fma2(dup2(hiB), wh, resB); }

// ---------- one full 3-layer path, two batch items at once ----------
// W1B: 25 pairs x 2 ulonglong2: [ (bias_pair | w_row0_pair), (w_row1_pair | pad) ]
// W2B: [bias: 5 quads][row r: 5 quads each], r = 0..49
// W3B: [bias pair][row r pair], r = 0..19   (u64 units)
template<int ACT, int ACTF>
__device__ __forceinline__ void path2(const ulonglong2* __restrict__ W1B,
                                      const ulonglong2* __restrict__ W2B,
                                      const u64* __restrict__ W3B,
                                      u64& hA, u64& hB)
{
    float xa0, xa1, xb0, xb1;
    upk2(hA, xa0, xa1); upk2(hB, xb0, xb1);
    u64 D0A = dup2(xa0), D1A = dup2(xa1);
    u64 D0B = dup2(xb0), D1B = dup2(xb1);

    u64 CA0, CA1, CA2, CA3, CA4, CA5, CA6, CA7, CA8, CA9;
    u64 CB0, CB1, CB2, CB3, CB4, CB5, CB6, CB7, CB8, CB9;
    { ulonglong2 b = W2B[0]; CA0 = b.x; CA1 = b.y; CB0 = b.x; CB1 = b.y; }
    { ulonglong2 b = W2B[1]; CA2 = b.x; CA3 = b.y; CB2 = b.x; CB3 = b.y; }
    { ulonglong2 b = W2B[2]; CA4 = b.x; CA5 = b.y; CB4 = b.x; CB5 = b.y; }
    { ulonglong2 b = W2B[3]; CA6 = b.x; CA7 = b.y; CB6 = b.x; CB7 = b.y; }
    { ulonglong2 b = W2B[4]; CA8 = b.x; CA9 = b.y; CB8 = b.x; CB9 = b.y; }

    const ulonglong2* p1 = W1B;
    const ulonglong2* p2 = W2B + 5;

    #pragma unroll 1
    for (int p = 0; p < 25; p++){
        // layer-1 output pair (outputs 2p, 2p+1) for both items
        ulonglong2 bw = p1[0];
        u64 w1 = ((const u64*)p1)[2];
        p1 += 2;
        u64 axA = fma2(D0A, bw.y, bw.x); axA = fma2(D1A, w1, axA); axA = act<ACT>(axA);
        u64 axB = fma2(D0B, bw.y, bw.x); axB = fma2(D1B, w1, axB); axB = act<ACT>(axB);
        float f0A, f1A, f0B, f1B;
        upk2(axA, f0A, f1A); upk2(axB, f0B, f1B);

        // scatter row 2p
        {
            u64 ddA = dup2(f0A), ddB = dup2(f0B);
            ulonglong2 q;
            q = p2[0]; SCAT(q, 0, 1)
            q = p2[1]; SCAT(q, 2, 3)
            q = p2[2]; SCAT(q, 4, 5)
            q = p2[3]; SCAT(q, 6, 7)
            q = p2[4]; SCAT(q, 8, 9)
        }
        // scatter row 2p+1
        {
            u64 ddA = dup2(f1A), ddB = dup2(f1B);
            ulonglong2 q;
            q = p2[5]; SCAT(q, 0, 1)
            q = p2[6]; SCAT(q, 2, 3)
            q = p2[7]; SCAT(q, 4, 5)
            q = p2[8]; SCAT(q, 6, 7)
            q = p2[9]; SCAT(q, 8, 9)
        }
        p2 += 10;
    }

    CA0 = act<ACT>(CA0); CA1 = act<ACT>(CA1); CA2 = act<ACT>(CA2); CA3 = act<ACT>(CA3);
    CA4 = act<ACT>(CA4); CA5 = act<ACT>(CA5); CA6 = act<ACT>(CA6); CA7 = act<ACT>(CA7);
    CA8 = act<ACT>(CA8); CA9 = act<ACT>(CA9);
    CB0 = act<ACT>(CB0); CB1 = act<ACT>(CB1); CB2 = act<ACT>(CB2); CB3 = act<ACT>(CB3);
    CB4 = act<ACT>(CB4); CB5 = act<ACT>(CB5); CB6 = act<ACT>(CB6); CB7 = act<ACT>(CB7);
    CB8 = act<ACT>(CB8); CB9 = act<ACT>(CB9);

    // layer 3: 20 inputs -> 1 packed output pair, both items
    u64 resA = W3B[0];
    u64 resB = resA;
    L3STEP(0,  1)
    L3STEP(1,  3)
    L3STEP(2,  5)
    L3STEP(3,  7)
    L3STEP(4,  9)
    L3STEP(5, 11)
    L3STEP(6, 13)
    L3STEP(7, 15)
    L3STEP(8, 17)
    L3STEP(9, 19)

    hA = act<ACTF>(resA);
    hB = act<ACTF>(resB);
}

// ---------- shared fills (element-wise scalar, no per-thread arrays) ----------
// L1 block: 25 pairs x 8 floats: {b[2p],b[2p+1], W[0][2p],W[0][2p+1], W[1][2p],W[1][2p+1], 0,0}
__device__ void fill_L1(float* dstf, const float* __restrict__ W,
                        const float* __restrict__ Bv)
{
    for (int e = threadIdx.x; e < 200; e += blockDim.x){
        int p = e >> 3, k = e & 7;
        float v = 0.0f;
        if      (k < 2) v = Bv[2*p + k];
        else if (k < 4) v = W[      2*p + (k-2)];   // row 0 of W[2][50]
        else if (k < 6) v = W[50 +  2*p + (k-4)];   // row 1
        dstf[e] = v;
    }
}
// L2 block (float view): [bias: 20][row r: 20 floats], r=0..49
__device__ void fill_L2(float* dstf, const float* __restrict__ W,
                        const float* __restrict__ Bv)
{
    for (int e = threadIdx.x; e < 1020; e += blockDim.x){
        int blk = e / 20, j = e % 20;
        dstf[e] = (blk == 0) ? Bv[j] : W[(blk - 1) * 20 + j];
    }
}
// L3 block (float view): [b0,b1][row r: W[2r], W[2r+1]], r=0..19
__device__ void fill_L3(float* dstf, const float* __restrict__ W,
                        const float* __restrict__ Bv)
{
    for (int e = threadIdx.x; e < 42; e += blockDim.x){
        int blk = e >> 1, j = e & 1;
        dstf[e] = (blk == 0) ? Bv[j] : W[(blk - 1) * 2 + j];
    }
}

// shared layout (ulonglong2 units): H1@0(50)  H2@50(255)  Z1@305(50)  Z2@355(255)
__global__ void __launch_bounds__(128)
recurrent_kernel(const float2* __restrict__ win,
                 const float* __restrict__ Wh1, const float* __restrict__ bh1,
                 const float* __restrict__ Wh2, const float* __restrict__ bh2,
                 const float* __restrict__ Wh3, const float* __restrict__ bh3,
                 const float* __restrict__ Wz1, const float* __restrict__ bz1,
                 const float* __restrict__ Wz2, const float* __restrict__ bz2,
                 const float* __restrict__ Wz3, const float* __restrict__ bz3,
                 float2* __restrict__ out, int half)
{
    __shared__ ulonglong2 sQ[610];
    __shared__ u64 sP[44];     // H3 @0 (21), Z3 @22 (21)

    fill_L1((float*)(sQ +   0), Wh1, bh1);
    fill_L2((float*)(sQ +  50), Wh2, bh2);
    fill_L1((float*)(sQ + 305), Wz1, bz1);
    fill_L2((float*)(sQ + 355), Wz2, bz2);
    fill_L3((float*)(sP +   0), Wh3, bh3);
    fill_L3((float*)(sP +  22), Wz3, bz3);
    __syncthreads();

    int tid = blockIdx.x * blockDim.x + threadIdx.x;
    if (tid >= half) return;

    float2 hinA = win[tid];
    float2 hinB = win[tid + half];
    u64 hA = pk2(hinA.x, hinA.y);
    u64 hB = pk2(hinB.x, hinB.y);

    float2* opA = out + (size_t)tid * 19;
    float2* opB = out + ((size_t)tid + half) * 19;

    #pragma unroll 1
    for (int t = 0; t < 19; t++){
        path2<0, 0>(sQ +   0, sQ +  50, sP +  0, hA, hB);   // h path: leaky relu
        u64 zA = hA, zB = hB;
        path2<1, 2>(sQ + 305, sQ + 355, sP + 22, zA, zB);   // z: tanh hidden, exact final
        float lo, hi;
        upk2(zA, lo, hi); opA[t] = make_float2(lo, hi);
        upk2(zB, lo, hi); opB[t] = make_float2(lo, hi);
    }
}

extern "C" void kernel_launch(void* const* d_in, const int* in_sizes, int n_in,
                              void* d_out, int out_size)
{
    const float* w   = (const float*)d_in[0];
    const float* Wh1 = (const float*)d_in[1];
    const float* bh1 = (const float*)d_in[2];
    const float* Wh2 = (const float*)d_in[3];
    const float* bh2 = (const float*)d_in[4];
    const float* Wh3 = (const float*)d_in[5];
    const float* bh3 = (const float*)d_in[6];
    const float* Wz1 = (const float*)d_in[7];
    const float* bz1 = (const float*)d_in[8];
    const float* Wz2 = (const float*)d_in[9];
    const float* bz2 = (const float*)d_in[10];
    const float* Wz3 = (const float*)d_in[11];
    const float* bz3 = (const float*)d_in[12];

    int B = in_sizes[0] / 2;
    int half = B / 2;                 // B = 1048576, even
    int threads = 128;
    int blocks = (half + threads - 1) / threads;
    recurrent_kernel<<<blocks, threads>>>((const float2*)w,
                                          Wh1, bh1, Wh2, bh2, Wh3, bh3,
                                          Wz1, bz1, Wz2, bz2, Wz3, bz3,
                                          (float2*)d_out, half);
}

// round 10
// speedup vs baseline: 1.2963x; 1.1083x over previous
#include <cuda_runtime.h>

typedef unsigned long long u64;

// ---------- packed f32x2 helpers ----------
__device__ __forceinline__ u64 fma2(u64 a, u64 b, u64 c){
    u64 d; asm("fma.rn.f32x2 %0, %1, %2, %3;" : "=l"(d) : "l"(a), "l"(b), "l"(c)); return d;
}
__device__ __forceinline__ u64 mul2(u64 a, u64 b){
    u64 d; asm("mul.rn.f32x2 %0, %1, %2;" : "=l"(d) : "l"(a), "l"(b)); return d;
}
__device__ __forceinline__ u64 pk2(float lo, float hi){
    u64 d; asm("mov.b64 %0, {%1, %2};" : "=l"(d) : "f"(lo), "f"(hi)); return d;
}
__device__ __forceinline__ void upk2(u64 v, float& lo, float& hi){
    asm("mov.b64 {%0, %1}, %2;" : "=f"(lo), "=f"(hi) : "l"(v));
}
__device__ __forceinline__ u64 dup2(float f){ return pk2(f, f); }

// leaky_relu(x) = 0.505*x + 0.495*|x| (slope 0.01), fully packed
__device__ __forceinline__ u64 act_lrelu(u64 v){
    u64 av = v & 0x7FFFFFFF7FFFFFFFULL;
    return fma2(av, 0x3EFD70A43EFD70A4ULL /*0.495*/, mul2(v, 0x3F0147AE3F0147AEULL /*0.505*/));
}
__device__ __forceinline__ float tanh_ap(float x){
    float r; asm("tanh.approx.f32 %0, %1;" : "=f"(r) : "f"(x)); return r;
}
// hidden-layer sigmoid: 0.5*tanh(x/2)+0.5
__device__ __forceinline__ u64 act_sigt(u64 v){
    const u64 half2 = 0x3F0000003F000000ULL;
    u64 v2 = mul2(v, half2);
    float lo, hi; upk2(v2, lo, hi);
    return fma2(pk2(tanh_ap(lo), tanh_ap(hi)), half2, half2);
}
// final-layer sigmoid: near-exact ex2+rcp
__device__ __forceinline__ float fast_sigmoid(float x){
    float e; asm("ex2.approx.f32 %0, %1;" : "=f"(e) : "f"(-1.44269504088896341f * x));
    float r; asm("rcp.approx.f32 %0, %1;" : "=f"(r) : "f"(1.0f + e));
    return r;
}
__device__ __forceinline__ u64 act_sige(u64 v){
    float lo, hi; upk2(v, lo, hi);
    return pk2(fast_sigmoid(lo), fast_sigmoid(hi));
}
// ACT codes: 0 = lrelu, 1 = tanh-sigmoid (hidden), 2 = exact sigmoid (final)
template<int ACT> __device__ __forceinline__ u64 act(u64 v){
    if (ACT == 0) return act_lrelu(v);
    else if (ACT == 1) return act_sigt(v);
    else return act_sige(v);
}

// scatter one loaded quad into all three items' accumulator pairs
#define SCAT(qv, a0, a1) \
    CA##a0 = fma2(ddA, (qv).x, CA##a0);  CB##a0 = fma2(ddB, (qv).x, CB##a0);  CC##a0 = fma2(ddC, (qv).x, CC##a0); \
    CA##a1 = fma2(ddA, (qv).y, CA##a1);  CB##a1 = fma2(ddB, (qv).y, CB##a1);  CC##a1 = fma2(ddC, (qv).y, CC##a1);

// layer-3 step for one accumulator pair (rows 2i, 2i+1), three items
#define L3STEP(Ci, wlo_idx) { \
    float loA, hiA, loB, hiB, loC, hiC; \
    upk2(CA##Ci, loA, hiA); upk2(CB##Ci, loB, hiB); upk2(CC##Ci, loC, hiC); \
    u64 wl = W3B[wlo_idx], wh = W3B[(wlo_idx)+1]; \
    resA = fma2(dup2(loA), wl, resA);  resB = fma2(dup2(loB), wl, resB);  resC = fma2(dup2(loC), wl, resC); \
    resA = fma2(dup2(hiA), wh, resA);  resB = fma2(dup2(hiB), wh, resB);  resC = fma2(dup2(hiC), wh, resC); }

// ---------- one full 3-layer path, THREE batch items at once ----------
// W1B: 25 pairs x 2 ulonglong2: [ (bias_pair | w_row0_pair), (w_row1_pair | pad) ]
// W2B: [bias: 5 quads][row r: 5 quads each], r = 0..49
// W3B: [bias pair][row r pair], r = 0..19   (u64 units)
template<int ACT, int ACTF>
__device__ __forceinline__ void path3(const ulonglong2* __restrict__ W1B,
                                      const ulonglong2* __restrict__ W2B,
                                      const u64* __restrict__ W3B,
                                      u64& hA, u64& hB, u64& hC)
{
    float xa0, xa1, xb0, xb1, xc0, xc1;
    upk2(hA, xa0, xa1); upk2(hB, xb0, xb1); upk2(hC, xc0, xc1);
    u64 D0A = dup2(xa0), D1A = dup2(xa1);
    u64 D0B = dup2(xb0), D1B = dup2(xb1);
    u64 D0C = dup2(xc0), D1C = dup2(xc1);

    u64 CA0, CA1, CA2, CA3, CA4, CA5, CA6, CA7, CA8, CA9;
    u64 CB0, CB1, CB2, CB3, CB4, CB5, CB6, CB7, CB8, CB9;
    u64 CC0, CC1, CC2, CC3, CC4, CC5, CC6, CC7, CC8, CC9;
    { ulonglong2 b = W2B[0]; CA0 = b.x; CA1 = b.y; CB0 = b.x; CB1 = b.y; CC0 = b.x; CC1 = b.y; }
    { ulonglong2 b = W2B[1]; CA2 = b.x; CA3 = b.y; CB2 = b.x; CB3 = b.y; CC2 = b.x; CC3 = b.y; }
    { ulonglong2 b = W2B[2]; CA4 = b.x; CA5 = b.y; CB4 = b.x; CB5 = b.y; CC4 = b.x; CC5 = b.y; }
    { ulonglong2 b = W2B[3]; CA6 = b.x; CA7 = b.y; CB6 = b.x; CB7 = b.y; CC6 = b.x; CC7 = b.y; }
    { ulonglong2 b = W2B[4]; CA8 = b.x; CA9 = b.y; CB8 = b.x; CB9 = b.y; CC8 = b.x; CC9 = b.y; }

    const ulonglong2* p1 = W1B;
    const ulonglong2* p2 = W2B + 5;

    #pragma unroll 1
    for (int p = 0; p < 25; p++){
        // layer-1 output pair (outputs 2p, 2p+1) for all items
        ulonglong2 bw = p1[0];
        u64 w1 = ((const u64*)p1)[2];
        p1 += 2;
        u64 axA = fma2(D0A, bw.y, bw.x); axA = fma2(D1A, w1, axA); axA = act<ACT>(axA);
        u64 axB = fma2(D0B, bw.y, bw.x); axB = fma2(D1B, w1, axB); axB = act<ACT>(axB);
        u64 axC = fma2(D0C, bw.y, bw.x); axC = fma2(D1C, w1, axC); axC = act<ACT>(axC);
        float f0A, f1A, f0B, f1B, f0C, f1C;
        upk2(axA, f0A, f1A); upk2(axB, f0B, f1B); upk2(axC, f0C, f1C);

        // scatter row 2p
        {
            u64 ddA = dup2(f0A), ddB = dup2(f0B), ddC = dup2(f0C);
            ulonglong2 q;
            q = p2[0]; SCAT(q, 0, 1)
            q = p2[1]; SCAT(q, 2, 3)
            q = p2[2]; SCAT(q, 4, 5)
            q = p2[3]; SCAT(q, 6, 7)
            q = p2[4]; SCAT(q, 8, 9)
        }
        // scatter row 2p+1
        {
            u64 ddA = dup2(f1A), ddB = dup2(f1B), ddC = dup2(f1C);
            ulonglong2 q;
            q = p2[5]; SCAT(q, 0, 1)
            q = p2[6]; SCAT(q, 2, 3)
            q = p2[7]; SCAT(q, 4, 5)
            q = p2[8]; SCAT(q, 6, 7)
            q = p2[9]; SCAT(q, 8, 9)
        }
        p2 += 10;
    }

    CA0 = act<ACT>(CA0); CA1 = act<ACT>(CA1); CA2 = act<ACT>(CA2); CA3 = act<ACT>(CA3);
    CA4 = act<ACT>(CA4); CA5 = act<ACT>(CA5); CA6 = act<ACT>(CA6); CA7 = act<ACT>(CA7);
    CA8 = act<ACT>(CA8); CA9 = act<ACT>(CA9);
    CB0 = act<ACT>(CB0); CB1 = act<ACT>(CB1); CB2 = act<ACT>(CB2); CB3 = act<ACT>(CB3);
    CB4 = act<ACT>(CB4); CB5 = act<ACT>(CB5); CB6 = act<ACT>(CB6); CB7 = act<ACT>(CB7);
    CB8 = act<ACT>(CB8); CB9 = act<ACT>(CB9);
    CC0 = act<ACT>(CC0); CC1 = act<ACT>(CC1); CC2 = act<ACT>(CC2); CC3 = act<ACT>(CC3);
    CC4 = act<ACT>(CC4); CC5 = act<ACT>(CC5); CC6 = act<ACT>(CC6); CC7 = act<ACT>(CC7);
    CC8 = act<ACT>(CC8); CC9 = act<ACT>(CC9);

    // layer 3: 20 inputs -> 1 packed output pair, all items
    u64 resA = W3B[0];
    u64 resB = resA;
    u64 resC = resA;
    L3STEP(0,  1)
    L3STEP(1,  3)
    L3STEP(2,  5)
    L3STEP(3,  7)
    L3STEP(4,  9)
    L3STEP(5, 11)
    L3STEP(6, 13)
    L3STEP(7, 15)
    L3STEP(8, 17)
    L3STEP(9, 19)

    hA = act<ACTF>(resA);
    hB = act<ACTF>(resB);
    hC = act<ACTF>(resC);
}

// ---------- shared fills (element-wise scalar, no per-thread arrays) ----------
// L1 block: 25 pairs x 8 floats: {b[2p],b[2p+1], W[0][2p],W[0][2p+1], W[1][2p],W[1][2p+1], 0,0}
__device__ void fill_L1(float* dstf, const float* __restrict__ W,
                        const float* __restrict__ Bv)
{
    for (int e = threadIdx.x; e < 200; e += blockDim.x){
        int p = e >> 3, k = e & 7;
        float v = 0.0f;
        if      (k < 2) v = Bv[2*p + k];
        else if (k < 4) v = W[      2*p + (k-2)];   // row 0 of W[2][50]
        else if (k < 6) v = W[50 +  2*p + (k-4)];   // row 1
        dstf[e] = v;
    }
}
// L2 block (float view): [bias: 20][row r: 20 floats], r=0..49
__device__ void fill_L2(float* dstf, const float* __restrict__ W,
                        const float* __restrict__ Bv)
{
    for (int e = threadIdx.x; e < 1020; e += blockDim.x){
        int blk = e / 20, j = e % 20;
        dstf[e] = (blk == 0) ? Bv[j] : W[(blk - 1) * 20 + j];
    }
}
// L3 block (float view): [b0,b1][row r: W[2r], W[2r+1]], r=0..19
__device__ void fill_L3(float* dstf, const float* __restrict__ W,
                        const float* __restrict__ Bv)
{
    for (int e = threadIdx.x; e < 42; e += blockDim.x){
        int blk = e >> 1, j = e & 1;
        dstf[e] = (blk == 0) ? Bv[j] : W[(blk - 1) * 2 + j];
    }
}

// shared layout (ulonglong2 units): H1@0(50)  H2@50(255)  Z1@305(50)  Z2@355(255)
__global__ void __launch_bounds__(128)
recurrent_kernel(const float2* __restrict__ win,
                 const float* __restrict__ Wh1, const float* __restrict__ bh1,
                 const float* __restrict__ Wh2, const float* __restrict__ bh2,
                 const float* __restrict__ Wh3, const float* __restrict__ bh3,
                 const float* __restrict__ Wz1, const float* __restrict__ bz1,
                 const float* __restrict__ Wz2, const float* __restrict__ bz2,
                 const float* __restrict__ Wz3, const float* __restrict__ bz3,
                 float2* __restrict__ out, int Q, int B)
{
    __shared__ ulonglong2 sQ[610];
    __shared__ u64 sP[44];     // H3 @0 (21), Z3 @22 (21)

    fill_L1((float*)(sQ +   0), Wh1, bh1);
    fill_L2((float*)(sQ +  50), Wh2, bh2);
    fill_L1((float*)(sQ + 305), Wz1, bz1);
    fill_L2((float*)(sQ + 355), Wz2, bz2);
    fill_L3((float*)(sP +   0), Wh3, bh3);
    fill_L3((float*)(sP +  22), Wz3, bz3);
    __syncthreads();

    int tid = blockIdx.x * blockDim.x + threadIdx.x;
    if (tid >= Q) return;

    int idxA = tid;
    int idxB = tid + Q;            // always < B (2Q <= B + pad small)
    int idxC = tid + 2 * Q;
    bool hasC = (idxC < B);
    int idxCl = hasC ? idxC : (B - 1);

    float2 hinA = win[idxA];
    float2 hinB = win[idxB];
    float2 hinC = win[idxCl];
    u64 hA = pk2(hinA.x, hinA.y);
    u64 hB = pk2(hinB.x, hinB.y);
    u64 hC = pk2(hinC.x, hinC.y);

    float2* opA = out + (size_t)idxA * 19;
    float2* opB = out + (size_t)idxB * 19;
    float2* opC = out + (size_t)idxCl * 19;

    #pragma unroll 1
    for (int t = 0; t < 19; t++){
        path3<0, 0>(sQ +   0, sQ +  50, sP +  0, hA, hB, hC);   // h path: leaky relu
        u64 zA = hA, zB = hB, zC = hC;
        path3<1, 2>(sQ + 305, sQ + 355, sP + 22, zA, zB, zC);   // z: tanh hidden, exact final
        float lo, hi;
        upk2(zA, lo, hi); opA[t] = make_float2(lo, hi);
        upk2(zB, lo, hi); opB[t] = make_float2(lo, hi);
        if (hasC) { upk2(zC, lo, hi); opC[t] = make_float2(lo, hi); }
    }
}

extern "C" void kernel_launch(void* const* d_in, const int* in_sizes, int n_in,
                              void* d_out, int out_size)
{
    const float* w   = (const float*)d_in[0];
    const float* Wh1 = (const float*)d_in[1];
    const float* bh1 = (const float*)d_in[2];
    const float* Wh2 = (const float*)d_in[3];
    const float* bh2 = (const float*)d_in[4];
    const float* Wh3 = (const float*)d_in[5];
    const float* bh3 = (const float*)d_in[6];
    const float* Wz1 = (const float*)d_in[7];
    const float* bz1 = (const float*)d_in[8];
    const float* Wz2 = (const float*)d_in[9];
    const float* bz2 = (const float*)d_in[10];
    const float* Wz3 = (const float*)d_in[11];
    const float* bz3 = (const float*)d_in[12];

    int B = in_sizes[0] / 2;            // 1048576
    int Q = (B + 2) / 3;                // items per segment (A,B full; C ragged)
    int threads = 128;
    int blocks = (Q + threads - 1) / threads;
    recurrent_kernel<<<blocks, threads>>>((const float2*)w,
                                          Wh1, bh1, Wh2, bh2, Wh3, bh3,
                                          Wz1, bz1, Wz2, bz2, Wz3, bz3,
                                          (float2*)d_out, Q, B);
}